// round 3
// baseline (speedup 1.0000x reference)
#include <cuda_runtime.h>
#include <stdint.h>

// ---------------- constants ----------------
#define NMAX     131072
#define NBUCKET  16384
#define NT       4          // 2x2 tiles
#define PMAX     2048
#define CANDMAX  4096
#define IMG_W    128
#define IMG_H    128
#define TSZ      64

// ---------------- device scratch (static, no allocs) ----------------
__device__ unsigned char       g_mask[NMAX];          // 4-bit tile overlap mask
__device__ unsigned short      g_bucket[NMAX];        // depth bucket
__device__ int                 g_bcount[NT * NBUCKET];// histogram -> prefix -> fill counters
__device__ int                 g_cutoff[NT];
__device__ int                 g_candTotal[NT];
__device__ unsigned long long  g_cand[NT * CANDMAX];  // (depth_bits<<32)|index
__device__ float4              g_gauss[NT * PMAX * 3];// packed per-tile sorted gaussians
__device__ int                 g_nvalid[NT];

// ---------------- kernel 0: zero histograms ----------------
__global__ void k_zero() {
    int i = blockIdx.x * blockDim.x + threadIdx.x;
    if (i < NT * NBUCKET) g_bcount[i] = 0;
}

// ---------------- kernel 1: per-gaussian rect/mask/bucket + histogram ----------------
__global__ void k_prep(const float* __restrict__ means,
                       const float* __restrict__ cov,
                       const float* __restrict__ depths, int N) {
    int i = blockIdx.x * blockDim.x + threadIdx.x;
    if (i >= N) return;
    float a = cov[4 * i + 0], b = cov[4 * i + 1];
    float c = cov[4 * i + 2], d = cov[4 * i + 3];
    float det = a * d - b * c;
    float mid = 0.5f * (a + d);
    float s   = sqrtf(fmaxf(mid * mid - det, 0.1f));
    float rad = 3.0f * ceilf(sqrtf(fmaxf(mid + s, mid - s)));
    float mx = means[2 * i], my = means[2 * i + 1];
    float xmin = fminf(fmaxf(mx - rad, 0.f), (float)(IMG_W - 1));
    float xmax = fminf(fmaxf(mx + rad, 0.f), (float)(IMG_W - 1));
    float ymin = fminf(fmaxf(my - rad, 0.f), (float)(IMG_H - 1));
    float ymax = fminf(fmaxf(my + rad, 0.f), (float)(IMG_H - 1));
    float dep = depths[i];
    int bucket = min(NBUCKET - 1, max(0, (int)(dep * 1600.0f)));
    unsigned mask = 0;
#pragma unroll
    for (int ty = 0; ty < 2; ty++) {
        float hmin = (float)(ty * TSZ), hmax = hmin + (float)(TSZ - 1);
        bool ovy = fminf(ymax, hmax) > fmaxf(ymin, hmin);
#pragma unroll
        for (int tx = 0; tx < 2; tx++) {
            float wmin = (float)(tx * TSZ), wmax = wmin + (float)(TSZ - 1);
            bool ovx = fminf(xmax, wmax) > fmaxf(xmin, wmin);
            if (ovx && ovy) {
                int t = ty * 2 + tx;
                mask |= 1u << t;
                atomicAdd(&g_bcount[t * NBUCKET + bucket], 1);
            }
        }
    }
    g_mask[i] = (unsigned char)mask;
    g_bucket[i] = (unsigned short)bucket;
}

// ---------------- kernel 2: per-tile prefix scan + rank-2048 cutoff ----------------
__global__ void k_scan() {
    int t = blockIdx.x;
    int* bc = g_bcount + t * NBUCKET;
    __shared__ int warpsum[8];
    __shared__ int s_running, s_cut, s_ctot;
    if (threadIdx.x == 0) { s_running = 0; s_cut = NBUCKET - 1; s_ctot = -1; }
    __syncthreads();
    int lane = threadIdx.x & 31, wid = threadIdx.x >> 5;
    for (int base = 0; base < NBUCKET; base += 256) {
        int i = base + threadIdx.x;
        int v = bc[i];
        int x = v;
#pragma unroll
        for (int o = 1; o < 32; o <<= 1) {
            int y = __shfl_up_sync(0xffffffffu, x, o);
            if (lane >= o) x += y;
        }
        if (lane == 31) warpsum[wid] = x;
        __syncthreads();
        if (threadIdx.x < 8) {
            int w = warpsum[threadIdx.x];
#pragma unroll
            for (int o = 1; o < 8; o <<= 1) {
                int y = __shfl_up_sync(0xffu, w, o);
                if ((int)threadIdx.x >= o) w += y;
            }
            warpsum[threadIdx.x] = w;
        }
        __syncthreads();
        int incl = x + (wid ? warpsum[wid - 1] : 0);
        int excl = incl - v;
        int run = s_running;
        int gE = run + excl, gI = run + incl;
        bc[i] = gE;                       // exclusive prefix (= scatter base)
        if (gE < PMAX && gI >= PMAX) { s_cut = i; s_ctot = gI; }
        __syncthreads();
        if (threadIdx.x == 0) s_running = run + warpsum[7];
        __syncthreads();
    }
    if (threadIdx.x == 0) {
        if (s_ctot < 0) { g_cutoff[t] = NBUCKET - 1; g_candTotal[t] = s_running; }
        else           { g_cutoff[t] = s_cut;        g_candTotal[t] = s_ctot; }
    }
}

// ---------------- kernel 3: scatter candidates (bucket <= cutoff) ----------------
__global__ void k_scatter(const float* __restrict__ depths, int N) {
    int i = blockIdx.x * blockDim.x + threadIdx.x;
    if (i >= N) return;
    unsigned mask = g_mask[i];
    if (!mask) return;
    int b = g_bucket[i];
    unsigned long long key =
        ((unsigned long long)__float_as_uint(depths[i]) << 32) | (unsigned)i;
#pragma unroll
    for (int t = 0; t < NT; t++) {
        if (((mask >> t) & 1) && b <= g_cutoff[t]) {
            int slot = atomicAdd(&g_bcount[t * NBUCKET + b], 1);
            if (slot < CANDMAX) g_cand[t * CANDMAX + slot] = key;
        }
    }
}

// ---------------- kernel 4: exact bitonic sort (depth, index) + gather/pack ----------------
__global__ void __launch_bounds__(1024) k_sort_gather(
        const float* __restrict__ means, const float* __restrict__ cov,
        const float* __restrict__ color, const float* __restrict__ opac) {
    __shared__ unsigned long long sk[CANDMAX];
    int t = blockIdx.x;
    int ctot = g_candTotal[t];
    int C = min(ctot, CANDMAX);
    for (int s = threadIdx.x; s < CANDMAX; s += 1024)
        sk[s] = (s < C) ? g_cand[t * CANDMAX + s] : 0xFFFFFFFFFFFFFFFFull;
    __syncthreads();
    for (int k = 2; k <= CANDMAX; k <<= 1) {
        for (int j = k >> 1; j > 0; j >>= 1) {
            for (int i = threadIdx.x; i < CANDMAX; i += 1024) {
                int ixj = i ^ j;
                if (ixj > i) {
                    bool up = ((i & k) == 0);
                    unsigned long long A = sk[i], B = sk[ixj];
                    if ((A > B) == up) { sk[i] = B; sk[ixj] = A; }
                }
            }
            __syncthreads();
        }
    }
    int nv = min(PMAX, ctot);
    for (int s = threadIdx.x; s < PMAX; s += 1024) {
        if (s < nv) {
            unsigned long long key = sk[s];
            int gi = (int)(unsigned)(key & 0xFFFFFFFFull);
            float dep = __uint_as_float((unsigned)(key >> 32));
            float a = cov[4 * gi + 0], b = cov[4 * gi + 1];
            float c = cov[4 * gi + 2], d = cov[4 * gi + 3];
            float invdet = 1.0f / fmaxf(a * d - b * c, 1e-6f);
            float4 q0 = make_float4(means[2 * gi], means[2 * gi + 1],
                                    d * invdet, -(b + c) * invdet);
            float4 q1 = make_float4(a * invdet, opac[gi], dep, 0.f);
            float4 q2 = make_float4(color[3 * gi], color[3 * gi + 1],
                                    color[3 * gi + 2], 0.f);
            int o = (t * PMAX + s) * 3;
            g_gauss[o + 0] = q0;
            g_gauss[o + 1] = q1;
            g_gauss[o + 2] = q2;
        }
    }
    if (threadIdx.x == 0) g_nvalid[t] = nv;
}

// ---------------- kernel 5: front-to-back compositing ----------------
// 256 CTAs x 64 threads. CTA = 2 warps; warp = 8x4 pixel patch (coherent early exit).
__global__ void __launch_bounds__(64) k_composite(float* __restrict__ out) {
    int tile = blockIdx.x >> 6;
    int ctaInTile = blockIdx.x & 63;
    int wid = threadIdx.x >> 5, lane = threadIdx.x & 31;
    int wTile = ctaInTile * 2 + wid;          // 0..127
    int patchX = wTile & 7, patchY = wTile >> 3;
    int lx = lane & 7, ly = lane >> 3;
    int tx = tile & 1, ty = tile >> 1;
    int pxi = tx * TSZ + patchX * 8 + lx;
    int pyi = ty * TSZ + patchY * 4 + ly;
    float pxf = (float)pxi, pyf = (float)pyi;

    int nv = g_nvalid[tile];
    const float4* gd = &g_gauss[tile * PMAX * 3];

    float T = 1.f, aR = 0.f, aG = 0.f, aB = 0.f, aD = 0.f, aA = 0.f;
    for (int g = 0; g < nv; ++g) {
        float4 q0 = __ldg(gd + 3 * g + 0);
        float4 q1 = __ldg(gd + 3 * g + 1);
        float4 q2 = __ldg(gd + 3 * g + 2);
        float dx = pxf - q0.x, dy = pyf - q0.y;
        float qd = dx * dx * q0.z + dy * dy * q1.x + dx * dy * q0.w;
        float alpha = fminf(__expf(-0.5f * qd) * q1.y, 0.99f);
        float w = alpha * T;
        aR += w * q2.x; aG += w * q2.y; aB += w * q2.z;
        aD += w * q1.z; aA += w;
        T *= (1.f - alpha);
        if (((g & 7) == 7) && __all_sync(0xffffffffu, T < 1e-6f)) break;
    }
    int pix = pyi * IMG_W + pxi;
    float bg = 1.f - aA;
    out[pix * 3 + 0] = aR + bg;
    out[pix * 3 + 1] = aG + bg;
    out[pix * 3 + 2] = aB + bg;
    out[IMG_W * IMG_H * 3 + pix] = aD;   // depth
    out[IMG_W * IMG_H * 4 + pix] = aA;   // alpha
}

// ---------------- launch ----------------
extern "C" void kernel_launch(void* const* d_in, const int* in_sizes, int n_in,
                              void* d_out, int out_size) {
    const float* means  = (const float*)d_in[0];
    const float* cov    = (const float*)d_in[1];
    const float* color  = (const float*)d_in[2];
    const float* opac   = (const float*)d_in[3];
    const float* depths = (const float*)d_in[4];
    int N = in_sizes[4];

    k_zero<<<(NT * NBUCKET + 1023) / 1024, 1024>>>();
    k_prep<<<(N + 255) / 256, 256>>>(means, cov, depths, N);
    k_scan<<<NT, 256>>>();
    k_scatter<<<(N + 255) / 256, 256>>>(depths, N);
    k_sort_gather<<<NT, 1024>>>(means, cov, color, opac);
    k_composite<<<256, 64>>>((float*)d_out);
}

// round 5
// speedup vs baseline: 3.1518x; 3.1518x over previous
#include <cuda_runtime.h>
#include <stdint.h>

// ---------------- constants ----------------
#define NMAX     131072
#define NBUCKET  16384
#define NT       4          // 2x2 tiles
#define PMAX     2048
#define CANDMAX  4096
#define IMG_W    128
#define IMG_H    128
#define TSZ      64
#define BINS     128        // per tile: 8 x-bins (8px) x 16 y-bins (4px)
#define BCAP     (PMAX + 4) // bin list capacity (incl. pad to multiple of 4)
#define GSTRIDE  ((PMAX + 1) * 3)   // float4s per tile in g_gauss (+1 dummy)

// ---------------- device scratch (static, no allocs) ----------------
__device__ unsigned char       g_mask[NMAX];
__device__ unsigned short      g_bucket[NMAX];
__device__ int                 g_bcount[NT * NBUCKET];
__device__ int                 g_cutoff[NT];
__device__ int                 g_candTotal[NT];
__device__ int                 g_nvalid[NT];
__device__ unsigned long long  g_cand[NT * CANDMAX];
__device__ float4              g_gauss[NT * GSTRIDE];
__device__ unsigned short      g_binIdx[NT * BINS * BCAP];
__device__ int                 g_binCnt[NT * BINS];

// ---------------- kernel 0: zero histograms ----------------
__global__ void k_zero() {
    int i = blockIdx.x * blockDim.x + threadIdx.x;
    if (i < NT * NBUCKET) g_bcount[i] = 0;
}

// ---------------- kernel 1: rect/mask/bucket + histogram ----------------
__global__ void k_prep(const float* __restrict__ means,
                       const float* __restrict__ cov,
                       const float* __restrict__ depths, int N) {
    int i = blockIdx.x * blockDim.x + threadIdx.x;
    if (i >= N) return;
    float a = cov[4 * i + 0], b = cov[4 * i + 1];
    float c = cov[4 * i + 2], d = cov[4 * i + 3];
    float det = a * d - b * c;
    float mid = 0.5f * (a + d);
    float s   = sqrtf(fmaxf(mid * mid - det, 0.1f));
    float rad = 3.0f * ceilf(sqrtf(fmaxf(mid + s, mid - s)));
    float mx = means[2 * i], my = means[2 * i + 1];
    float xmin = fminf(fmaxf(mx - rad, 0.f), (float)(IMG_W - 1));
    float xmax = fminf(fmaxf(mx + rad, 0.f), (float)(IMG_W - 1));
    float ymin = fminf(fmaxf(my - rad, 0.f), (float)(IMG_H - 1));
    float ymax = fminf(fmaxf(my + rad, 0.f), (float)(IMG_H - 1));
    float dep = depths[i];
    int bucket = min(NBUCKET - 1, max(0, (int)(dep * 1600.0f)));
    unsigned mask = 0;
#pragma unroll
    for (int ty = 0; ty < 2; ty++) {
        float hmin = (float)(ty * TSZ), hmax = hmin + (float)(TSZ - 1);
        bool ovy = fminf(ymax, hmax) > fmaxf(ymin, hmin);
#pragma unroll
        for (int tx = 0; tx < 2; tx++) {
            float wmin = (float)(tx * TSZ), wmax = wmin + (float)(TSZ - 1);
            bool ovx = fminf(xmax, wmax) > fmaxf(xmin, wmin);
            if (ovx && ovy) {
                int t = ty * 2 + tx;
                mask |= 1u << t;
                atomicAdd(&g_bcount[t * NBUCKET + bucket], 1);
            }
        }
    }
    g_mask[i] = (unsigned char)mask;
    g_bucket[i] = (unsigned short)bucket;
}

// ---------------- kernel 2: per-tile prefix scan + rank-2048 cutoff ----------------
__global__ void k_scan() {
    int t = blockIdx.x;
    int* bc = g_bcount + t * NBUCKET;
    __shared__ int warpsum[8];
    __shared__ int s_running, s_cut, s_ctot;
    if (threadIdx.x == 0) { s_running = 0; s_cut = NBUCKET - 1; s_ctot = -1; }
    __syncthreads();
    int lane = threadIdx.x & 31, wid = threadIdx.x >> 5;
    for (int base = 0; base < NBUCKET; base += 256) {
        int i = base + threadIdx.x;
        int v = bc[i];
        int x = v;
#pragma unroll
        for (int o = 1; o < 32; o <<= 1) {
            int y = __shfl_up_sync(0xffffffffu, x, o);
            if (lane >= o) x += y;
        }
        if (lane == 31) warpsum[wid] = x;
        __syncthreads();
        if (threadIdx.x < 8) {
            int w = warpsum[threadIdx.x];
#pragma unroll
            for (int o = 1; o < 8; o <<= 1) {
                int y = __shfl_up_sync(0xffu, w, o);
                if ((int)threadIdx.x >= o) w += y;
            }
            warpsum[threadIdx.x] = w;
        }
        __syncthreads();
        int incl = x + (wid ? warpsum[wid - 1] : 0);
        int excl = incl - v;
        int run = s_running;
        int gE = run + excl, gI = run + incl;
        bc[i] = gE;                       // exclusive prefix (scatter base)
        if (gE < PMAX && gI >= PMAX) { s_cut = i; s_ctot = gI; }
        __syncthreads();
        if (threadIdx.x == 0) s_running = run + warpsum[7];
        __syncthreads();
    }
    if (threadIdx.x == 0) {
        int ctot, cut;
        if (s_ctot < 0) { cut = NBUCKET - 1; ctot = s_running; }
        else            { cut = s_cut;       ctot = s_ctot;    }
        g_cutoff[t] = cut;
        g_candTotal[t] = ctot;
        g_nvalid[t] = min(PMAX, ctot);
    }
}

// ---------------- kernel 3: scatter candidates (bucket <= cutoff) ----------------
__global__ void k_scatter(const float* __restrict__ depths, int N) {
    int i = blockIdx.x * blockDim.x + threadIdx.x;
    if (i >= N) return;
    unsigned mask = g_mask[i];
    if (!mask) return;
    int b = g_bucket[i];
    unsigned long long key =
        ((unsigned long long)__float_as_uint(depths[i]) << 32) | (unsigned)i;
#pragma unroll
    for (int t = 0; t < NT; t++) {
        if (((mask >> t) & 1) && b <= g_cutoff[t]) {
            int slot = atomicAdd(&g_bcount[t * NBUCKET + b], 1);
            if (slot < CANDMAX) g_cand[t * CANDMAX + slot] = key;
        }
    }
}

// ---------------- kernel 4: per-bucket insertion sort (buckets are tiny) ----------
// After scatter, g_bcount[b] = inclusive prefix (start of bucket b+1).
// Bucket b occupies [b?bc[b-1]:0, bc[b]). Sorting each bucket by full key
// (depth_bits, idx) + bucket-major order == exact stable global depth sort.
__global__ void k_bsort() {
    int t = blockIdx.x;
    int cut = g_cutoff[t];
    unsigned long long* A = g_cand + t * CANDMAX;
    const int* bc = g_bcount + t * NBUCKET;
    for (int b = threadIdx.x; b <= cut; b += blockDim.x) {
        int start = b ? bc[b - 1] : 0;
        int end = min(bc[b], CANDMAX);
        for (int i = start + 1; i < end; i++) {
            unsigned long long key = A[i];
            int j = i - 1;
            while (j >= start && A[j] > key) { A[j + 1] = A[j]; j--; }
            A[j + 1] = key;
        }
    }
}

// ---------------- kernel 5: gather + pack (conic pre-scaled for exp2) ----------
__global__ void k_gather(const float* __restrict__ means, const float* __restrict__ cov,
                         const float* __restrict__ color, const float* __restrict__ opac) {
    int id = blockIdx.x * blockDim.x + threadIdx.x;
    if (id >= NT * (PMAX + 1)) return;
    int t = id / (PMAX + 1);
    int s = id - t * (PMAX + 1);
    float4* out = g_gauss + t * GSTRIDE;
    if (s == PMAX) {  // neutral dummy (op = 0): used for list padding
        out[3 * PMAX + 0] = make_float4(0.f, 0.f, 0.f, 0.f);
        out[3 * PMAX + 1] = make_float4(0.f, 0.f, -1000.f, 0.f);
        out[3 * PMAX + 2] = make_float4(0.f, 0.f, 0.f, 0.f);
        return;
    }
    if (s >= g_nvalid[t]) return;
    unsigned long long key = g_cand[t * CANDMAX + s];
    int gi = (int)(unsigned)(key & 0xFFFFFFFFull);
    float dep = __uint_as_float((unsigned)(key >> 32));
    float a = cov[4 * gi + 0], b = cov[4 * gi + 1];
    float c = cov[4 * gi + 2], d = cov[4 * gi + 3];
    float invdet = 1.0f / fmaxf(a * d - b * c, 1e-6f);
    const float S = -0.7213475204444817f;      // -0.5 * log2(e)
    float c00s = S * d * invdet;
    float c11s = S * a * invdet;
    float c01s = -S * (b + c) * invdet;
    float op = opac[gi];
    out[3 * s + 0] = make_float4(-means[2 * gi], -means[2 * gi + 1], c00s, c11s);
    out[3 * s + 1] = make_float4(c01s, op, log2f(fmaxf(op, 1e-38f)), 0.f);
    out[3 * s + 2] = make_float4(color[3 * gi], color[3 * gi + 1], color[3 * gi + 2], dep);
}

// ---------------- kernel 6: per-bin culling (order-preserving compaction) ------
// Bin = 8x4 pixels. Keep entry iff conservative max over the bin of
// log2(alpha) = c00s*dx^2 + c11s*dy^2 + c01s*dx*dy + log2(op) > -27.
__global__ void __launch_bounds__(128) k_bin() {
    int wg = blockIdx.x * 4 + (threadIdx.x >> 5);   // 512 warps = NT*BINS
    int lane = threadIdx.x & 31;
    int t = wg >> 7, b = wg & 127;
    int bx = b & 7, by = b >> 3;
    float x0 = (float)((t & 1) * TSZ + bx * 8), x1 = x0 + 7.f;
    float y0 = (float)((t >> 1) * TSZ + by * 4), y1 = y0 + 3.f;
    int nv = g_nvalid[t];
    const float4* gd = g_gauss + t * GSTRIDE;
    unsigned short* list = g_binIdx + (t * BINS + b) * BCAP;
    int cnt = 0;
    for (int base = 0; base < nv; base += 32) {
        int g = base + lane;
        bool keep = false;
        if (g < nv) {
            float4 q0 = __ldg(gd + 3 * g);
            float4 q1 = __ldg(gd + 3 * g + 1);
            float ax = x0 + q0.x, bxx = x1 + q0.x;   // dx interval
            float ay = y0 + q0.y, byy = y1 + q0.y;   // dy interval
            float msx = (ax <= 0.f && bxx >= 0.f) ? 0.f : fminf(ax * ax, bxx * bxx);
            float msy = (ay <= 0.f && byy >= 0.f) ? 0.f : fminf(ay * ay, byy * byy);
            float p1 = ax * ay, p2 = ax * byy, p3 = bxx * ay, p4 = bxx * byy;
            float pmax = fmaxf(fmaxf(p1, p2), fmaxf(p3, p4));
            float pmin = fminf(fminf(p1, p2), fminf(p3, p4));
            float cross = q1.x * ((q1.x > 0.f) ? pmax : pmin);
            float bound = q0.z * msx + q0.w * msy + cross + q1.z;
            keep = bound > -27.f;
        }
        unsigned bal = __ballot_sync(0xffffffffu, keep);
        int pos = cnt + __popc(bal & ((1u << lane) - 1u));
        if (keep) list[pos] = (unsigned short)g;
        cnt += __popc(bal);
    }
    if (lane == 0) {
        while (cnt & 3) list[cnt++] = (unsigned short)PMAX;  // pad with dummy
        g_binCnt[t * BINS + b] = cnt;
    }
}

// ---------------- kernel 7: compositing (warp = its bin, unroll 4) -------------
__global__ void __launch_bounds__(64) k_composite(float* __restrict__ out) {
    int wg = blockIdx.x * 2 + (threadIdx.x >> 5);
    int lane = threadIdx.x & 31;
    int t = wg >> 7, b = wg & 127;
    int bx = b & 7, by = b >> 3;
    int px = (t & 1) * TSZ + bx * 8 + (lane & 7);
    int py = (t >> 1) * TSZ + by * 4 + (lane >> 3);
    float pxf = (float)px, pyf = (float)py;
    int n = g_binCnt[t * BINS + b];                 // multiple of 4
    const float4* gd = g_gauss + t * GSTRIDE;
    const unsigned short* list = g_binIdx + (t * BINS + b) * BCAP;

    float T = 1.f, aR = 0.f, aG = 0.f, aB = 0.f, aD = 0.f, aA = 0.f;
    for (int g0 = 0; g0 < n; g0 += 4) {
        ushort4 i4 = *reinterpret_cast<const ushort4*>(list + g0);
#pragma unroll
        for (int u = 0; u < 4; ++u) {
            int idx = (u == 0) ? i4.x : (u == 1) ? i4.y : (u == 2) ? i4.z : i4.w;
            float4 q0 = __ldg(gd + 3 * idx);
            float4 q1 = __ldg(gd + 3 * idx + 1);
            float4 q2 = __ldg(gd + 3 * idx + 2);
            float dx = pxf + q0.x, dy = pyf + q0.y;
            float e = exp2f(fmaf(dx * dy, q1.x, fmaf(dy * dy, q0.w, dx * dx * q0.z)));
            float alpha = fminf(e * q1.y, 0.99f);
            float w = alpha * T;
            aR = fmaf(w, q2.x, aR);
            aG = fmaf(w, q2.y, aG);
            aB = fmaf(w, q2.z, aB);
            aD = fmaf(w, q2.w, aD);
            aA += w;
            T -= w;                                  // T *= (1 - alpha) exactly
        }
        if (__all_sync(0xffffffffu, T < 1e-5f)) break;
    }
    int pix = py * IMG_W + px;
    float bg = 1.f - aA;
    out[pix * 3 + 0] = aR + bg;
    out[pix * 3 + 1] = aG + bg;
    out[pix * 3 + 2] = aB + bg;
    out[IMG_W * IMG_H * 3 + pix] = aD;
    out[IMG_W * IMG_H * 4 + pix] = aA;
}

// ---------------- launch ----------------
extern "C" void kernel_launch(void* const* d_in, const int* in_sizes, int n_in,
                              void* d_out, int out_size) {
    const float* means  = (const float*)d_in[0];
    const float* cov    = (const float*)d_in[1];
    const float* color  = (const float*)d_in[2];
    const float* opac   = (const float*)d_in[3];
    const float* depths = (const float*)d_in[4];
    int N = in_sizes[4];

    k_zero<<<(NT * NBUCKET + 1023) / 1024, 1024>>>();
    k_prep<<<(N + 255) / 256, 256>>>(means, cov, depths, N);
    k_scan<<<NT, 256>>>();
    k_scatter<<<(N + 255) / 256, 256>>>(depths, N);
    k_bsort<<<NT, 256>>>();
    k_gather<<<(NT * (PMAX + 1) + 255) / 256, 256>>>(means, cov, color, opac);
    k_bin<<<BINS, 128>>>();                 // 128 CTAs x 4 warps = 512 bins
    k_composite<<<256, 64>>>((float*)d_out);
}

// round 9
// speedup vs baseline: 7.6727x; 2.4344x over previous
#include <cuda_runtime.h>
#include <stdint.h>

// ---------------- constants ----------------
#define NMAX     131072
#define NBUCKET  16384
#define NT       4          // 2x2 tiles
#define PMAX     2048
#define CANDMAX  4096
#define IMG_W    128
#define IMG_H    128
#define TSZ      64
#define BINS     128        // per tile: 8 x-bins (8px) x 16 y-bins (4px)
#define GSTRIDE  ((PMAX + 1) * 3)   // float4s per tile in g_gauss (+1 dummy)

// ---------------- device scratch (static, no allocs) ----------------
__device__ unsigned char       g_mask[NMAX];
__device__ unsigned short      g_bucket[NMAX];
__device__ int                 g_bcount[NT * NBUCKET];
__device__ int                 g_cutoff[NT];
__device__ int                 g_nvalid[NT];
__device__ unsigned long long  g_cand[NT * CANDMAX];
__device__ float4              g_gauss[NT * GSTRIDE];

// ---------------- kernel 0: zero histograms ----------------
__global__ void k_zero() {
    int i = blockIdx.x * blockDim.x + threadIdx.x;
    if (i < NT * NBUCKET) g_bcount[i] = 0;
}

// ---------------- kernel 1: rect/mask/bucket + histogram ----------------
__global__ void k_prep(const float2* __restrict__ means,
                       const float4* __restrict__ cov,
                       const float* __restrict__ depths, int N) {
    int i = blockIdx.x * blockDim.x + threadIdx.x;
    if (i >= N) return;
    float4 cv = cov[i];
    float a = cv.x, b = cv.y, c = cv.z, d = cv.w;
    float det = a * d - b * c;
    float mid = 0.5f * (a + d);
    float s   = sqrtf(fmaxf(mid * mid - det, 0.1f));
    float rad = 3.0f * ceilf(sqrtf(fmaxf(mid + s, mid - s)));
    float2 mn = means[i];
    float xmin = fminf(fmaxf(mn.x - rad, 0.f), (float)(IMG_W - 1));
    float xmax = fminf(fmaxf(mn.x + rad, 0.f), (float)(IMG_W - 1));
    float ymin = fminf(fmaxf(mn.y - rad, 0.f), (float)(IMG_H - 1));
    float ymax = fminf(fmaxf(mn.y + rad, 0.f), (float)(IMG_H - 1));
    float dep = depths[i];
    int bucket = min(NBUCKET - 1, max(0, (int)(dep * 1600.0f)));
    unsigned mask = 0;
#pragma unroll
    for (int ty = 0; ty < 2; ty++) {
        float hmin = (float)(ty * TSZ), hmax = hmin + (float)(TSZ - 1);
        bool ovy = fminf(ymax, hmax) > fmaxf(ymin, hmin);
#pragma unroll
        for (int tx = 0; tx < 2; tx++) {
            float wmin = (float)(tx * TSZ), wmax = wmin + (float)(TSZ - 1);
            bool ovx = fminf(xmax, wmax) > fmaxf(xmin, wmin);
            if (ovx && ovy) {
                int t = ty * 2 + tx;
                mask |= 1u << t;
                atomicAdd(&g_bcount[t * NBUCKET + bucket], 1);
            }
        }
    }
    g_mask[i] = (unsigned char)mask;
    g_bucket[i] = (unsigned short)bucket;
}

// ---------------- kernel 2: per-tile prefix scan + rank-2048 cutoff --------
// Breaks as soon as the running total reaches PMAX: buckets past the cutoff
// are never read downstream, so this is exact. Typically ~4 chunks, not 64.
__global__ void k_scan() {
    int t = blockIdx.x;
    int* bc = g_bcount + t * NBUCKET;
    __shared__ int warpsum[8];
    __shared__ int s_running, s_cut, s_ctot;
    if (threadIdx.x == 0) { s_running = 0; s_cut = NBUCKET - 1; s_ctot = -1; }
    __syncthreads();
    int lane = threadIdx.x & 31, wid = threadIdx.x >> 5;
    for (int base = 0; base < NBUCKET; base += 256) {
        int i = base + threadIdx.x;
        int v = bc[i];
        int x = v;
#pragma unroll
        for (int o = 1; o < 32; o <<= 1) {
            int y = __shfl_up_sync(0xffffffffu, x, o);
            if (lane >= o) x += y;
        }
        if (lane == 31) warpsum[wid] = x;
        __syncthreads();
        if (threadIdx.x < 8) {
            int w = warpsum[threadIdx.x];
#pragma unroll
            for (int o = 1; o < 8; o <<= 1) {
                int y = __shfl_up_sync(0xffu, w, o);
                if ((int)threadIdx.x >= o) w += y;
            }
            warpsum[threadIdx.x] = w;
        }
        __syncthreads();
        int incl = x + (wid ? warpsum[wid - 1] : 0);
        int excl = incl - v;
        int run = s_running;
        int gE = run + excl, gI = run + incl;
        bc[i] = gE;                       // exclusive prefix (scatter base)
        if (gE < PMAX && gI >= PMAX) { s_cut = i; s_ctot = gI; }
        __syncthreads();
        if (threadIdx.x == 0) s_running = run + warpsum[7];
        __syncthreads();
        if (s_running >= PMAX) break;     // cutoff found: rest is dead weight
    }
    if (threadIdx.x == 0) {
        int ctot, cut;
        if (s_ctot < 0) { cut = NBUCKET - 1; ctot = s_running; }
        else            { cut = s_cut;       ctot = s_ctot;    }
        g_cutoff[t] = cut;
        g_nvalid[t] = min(PMAX, ctot);
    }
}

// ---------------- kernel 3: scatter candidates (bucket <= cutoff) ----------
__global__ void k_scatter(const float* __restrict__ depths, int N) {
    int i = blockIdx.x * blockDim.x + threadIdx.x;
    if (i >= N) return;
    unsigned mask = g_mask[i];
    if (!mask) return;
    int b = g_bucket[i];
    int c0 = __ldg(&g_cutoff[0]), c1 = __ldg(&g_cutoff[1]);
    int c2 = __ldg(&g_cutoff[2]), c3 = __ldg(&g_cutoff[3]);
    bool p0 = (mask & 1u) && b <= c0;
    bool p1 = (mask & 2u) && b <= c1;
    bool p2 = (mask & 4u) && b <= c2;
    bool p3 = (mask & 8u) && b <= c3;
    if (!(p0 | p1 | p2 | p3)) return;
    unsigned long long key =
        ((unsigned long long)__float_as_uint(__ldg(&depths[i])) << 32) | (unsigned)i;
    if (p0) { int s = atomicAdd(&g_bcount[0 * NBUCKET + b], 1); if (s < CANDMAX) g_cand[0 * CANDMAX + s] = key; }
    if (p1) { int s = atomicAdd(&g_bcount[1 * NBUCKET + b], 1); if (s < CANDMAX) g_cand[1 * CANDMAX + s] = key; }
    if (p2) { int s = atomicAdd(&g_bcount[2 * NBUCKET + b], 1); if (s < CANDMAX) g_cand[2 * CANDMAX + s] = key; }
    if (p3) { int s = atomicAdd(&g_bcount[3 * NBUCKET + b], 1); if (s < CANDMAX) g_cand[3 * CANDMAX + s] = key; }
}

// ---------------- kernel 4: per-bucket sort + gather/pack (fused) ----------
// Phase 1: insertion-sort each tiny depth bucket in place (bucket-major order
// + per-bucket full-key sort == exact stable global argsort for positive
// floats). Phase 2: gather gaussian params into packed per-tile arrays.
__global__ void __launch_bounds__(1024) k_sortgather(
        const float2* __restrict__ means, const float4* __restrict__ cov,
        const float* __restrict__ color, const float* __restrict__ opac) {
    int t = blockIdx.x;
    int cut = g_cutoff[t];
    unsigned long long* A = g_cand + t * CANDMAX;
    const int* bc = g_bcount + t * NBUCKET;
    for (int b = threadIdx.x; b <= cut; b += 1024) {
        int start = b ? bc[b - 1] : 0;
        int end = min(bc[b], CANDMAX);
        for (int i = start + 1; i < end; i++) {
            unsigned long long key = A[i];
            int j = i - 1;
            while (j >= start && A[j] > key) { A[j + 1] = A[j]; j--; }
            A[j + 1] = key;
        }
    }
    __syncthreads();
    int nv = g_nvalid[t];
    float4* out = g_gauss + t * GSTRIDE;
    const float S = -0.7213475204444817f;      // -0.5 * log2(e)
    for (int s = threadIdx.x; s <= PMAX; s += 1024) {
        if (s == PMAX) {                       // neutral dummy (op = 0)
            out[3 * PMAX + 0] = make_float4(0.f, 0.f, 0.f, 0.f);
            out[3 * PMAX + 1] = make_float4(0.f, 0.f, -1000.f, 0.f);
            out[3 * PMAX + 2] = make_float4(0.f, 0.f, 0.f, 0.f);
        } else if (s < nv) {
            unsigned long long key = A[s];
            int gi = (int)(unsigned)(key & 0xFFFFFFFFull);
            float dep = __uint_as_float((unsigned)(key >> 32));
            float4 cv = cov[gi];
            float invdet = 1.0f / fmaxf(cv.x * cv.w - cv.y * cv.z, 1e-6f);
            float c00s = S * cv.w * invdet;
            float c11s = S * cv.x * invdet;
            float c01s = -S * (cv.y + cv.z) * invdet;
            float op = opac[gi];
            float2 mn = means[gi];
            out[3 * s + 0] = make_float4(-mn.x, -mn.y, c00s, c11s);
            out[3 * s + 1] = make_float4(c01s, op, __log2f(fmaxf(op, 1e-38f)), 0.f);
            out[3 * s + 2] = make_float4(color[3 * gi], color[3 * gi + 1],
                                         color[3 * gi + 2], dep);
        }
    }
}

// ---------------- kernel 5: fused cull + composite -------------------------
// Warp = 8x4 pixel bin. Per 32-gaussian chunk: every lane tests one gaussian
// against the bin (conservative log2-alpha bound), ballot-compacts survivors
// into a 64-entry smem ring, drains the ring in unroll-4 groups. Early exit
// (T saturated warp-wide) terminates BOTH the composite and the cull scan.
__global__ void __launch_bounds__(64) k_composite(float* __restrict__ out) {
    __shared__ __align__(16) unsigned short sbuf[2][64];
    int wid = threadIdx.x >> 5, lane = threadIdx.x & 31;
    int wg = blockIdx.x * 2 + wid;
    int t = wg >> 7, b = wg & 127;
    int bx = b & 7, by = b >> 3;
    int px = (t & 1) * TSZ + bx * 8 + (lane & 7);
    int py = (t >> 1) * TSZ + by * 4 + (lane >> 3);
    float pxf = (float)px, pyf = (float)py;
    float x0 = (float)((t & 1) * TSZ + bx * 8), x1 = x0 + 7.f;
    float y0 = (float)((t >> 1) * TSZ + by * 4), y1 = y0 + 3.f;

    int nv = g_nvalid[t];
    const float4* gd = g_gauss + t * GSTRIDE;

    float T = 1.f, aR = 0.f, aG = 0.f, aB = 0.f, aD = 0.f, aA = 0.f;
    int head = 0, tail = 0;

    for (int base = 0; base < nv; base += 32) {
        int g = base + lane;
        bool keep = false;
        if (g < nv) {
            float4 q0 = __ldg(gd + 3 * g);
            float4 q1 = __ldg(gd + 3 * g + 1);
            float ax = x0 + q0.x, bxx = x1 + q0.x;   // dx interval
            float ay = y0 + q0.y, byy = y1 + q0.y;   // dy interval
            float msx = (ax <= 0.f && bxx >= 0.f) ? 0.f : fminf(ax * ax, bxx * bxx);
            float msy = (ay <= 0.f && byy >= 0.f) ? 0.f : fminf(ay * ay, byy * byy);
            float p1 = ax * ay, p2 = ax * byy, p3 = bxx * ay, p4 = bxx * byy;
            float pmax = fmaxf(fmaxf(p1, p2), fmaxf(p3, p4));
            float pmin = fminf(fminf(p1, p2), fminf(p3, p4));
            float cross = q1.x * ((q1.x > 0.f) ? pmax : pmin);
            float bound = q0.z * msx + q0.w * msy + cross + q1.z;
            keep = bound > -27.f;
        }
        unsigned bal = __ballot_sync(0xffffffffu, keep);
        int pos = head + __popc(bal & ((1u << lane) - 1u));
        if (keep) sbuf[wid][pos & 63] = (unsigned short)g;
        head += __popc(bal);
        __syncwarp();
        while (head - tail >= 4) {
            ushort4 i4 = *reinterpret_cast<const ushort4*>(&sbuf[wid][tail & 63]);
            tail += 4;
#pragma unroll
            for (int u = 0; u < 4; ++u) {
                int idx = (u == 0) ? i4.x : (u == 1) ? i4.y : (u == 2) ? i4.z : i4.w;
                float4 q0 = __ldg(gd + 3 * idx);
                float4 q1 = __ldg(gd + 3 * idx + 1);
                float4 q2 = __ldg(gd + 3 * idx + 2);
                float dx = pxf + q0.x, dy = pyf + q0.y;
                float e = exp2f(fmaf(dx * dy, q1.x, fmaf(dy * dy, q0.w, dx * dx * q0.z)));
                float alpha = fminf(e * q1.y, 0.99f);
                float w = alpha * T;
                aR = fmaf(w, q2.x, aR);
                aG = fmaf(w, q2.y, aG);
                aB = fmaf(w, q2.z, aB);
                aD = fmaf(w, q2.w, aD);
                aA += w;
                T -= w;                              // T *= (1 - alpha) exactly
            }
        }
        if (__all_sync(0xffffffffu, T < 1e-5f)) { tail = head; break; }
    }
    // flush remainder (pad ring with dummy PMAX entries to a multiple of 4)
    if (head - tail) {
        int pad = (4 - ((head - tail) & 3)) & 3;
        if (lane < pad) sbuf[wid][(head + lane) & 63] = (unsigned short)PMAX;
        head += pad;
        __syncwarp();
        while (head - tail >= 4) {
            ushort4 i4 = *reinterpret_cast<const ushort4*>(&sbuf[wid][tail & 63]);
            tail += 4;
#pragma unroll
            for (int u = 0; u < 4; ++u) {
                int idx = (u == 0) ? i4.x : (u == 1) ? i4.y : (u == 2) ? i4.z : i4.w;
                float4 q0 = __ldg(gd + 3 * idx);
                float4 q1 = __ldg(gd + 3 * idx + 1);
                float4 q2 = __ldg(gd + 3 * idx + 2);
                float dx = pxf + q0.x, dy = pyf + q0.y;
                float e = exp2f(fmaf(dx * dy, q1.x, fmaf(dy * dy, q0.w, dx * dx * q0.z)));
                float alpha = fminf(e * q1.y, 0.99f);
                float w = alpha * T;
                aR = fmaf(w, q2.x, aR);
                aG = fmaf(w, q2.y, aG);
                aB = fmaf(w, q2.z, aB);
                aD = fmaf(w, q2.w, aD);
                aA += w;
                T -= w;
            }
        }
    }
    int pix = py * IMG_W + px;
    float bg = 1.f - aA;
    out[pix * 3 + 0] = aR + bg;
    out[pix * 3 + 1] = aG + bg;
    out[pix * 3 + 2] = aB + bg;
    out[IMG_W * IMG_H * 3 + pix] = aD;
    out[IMG_W * IMG_H * 4 + pix] = aA;
}

// ---------------- launch ----------------
extern "C" void kernel_launch(void* const* d_in, const int* in_sizes, int n_in,
                              void* d_out, int out_size) {
    const float* means  = (const float*)d_in[0];
    const float* cov    = (const float*)d_in[1];
    const float* color  = (const float*)d_in[2];
    const float* opac   = (const float*)d_in[3];
    const float* depths = (const float*)d_in[4];
    int N = in_sizes[4];

    k_zero<<<(NT * NBUCKET + 1023) / 1024, 1024>>>();
    k_prep<<<(N + 255) / 256, 256>>>((const float2*)means, (const float4*)cov, depths, N);
    k_scan<<<NT, 256>>>();
    k_scatter<<<(N + 255) / 256, 256>>>(depths, N);
    k_sortgather<<<NT, 1024>>>((const float2*)means, (const float4*)cov, color, opac);
    k_composite<<<256, 64>>>((float*)d_out);
}

// round 10
// speedup vs baseline: 12.1600x; 1.5848x over previous
#include <cuda_runtime.h>
#include <stdint.h>

// ---------------- constants ----------------
#define NMAX     131072
#define NBUCKET  16384
#define NT       4          // 2x2 tiles
#define PMAX     2048
#define CANDMAX  4096
#define IMG_W    128
#define IMG_H    128
#define TSZ      64
#define BINS     128        // per tile: 8 x-bins (8px) x 16 y-bins (4px)
#define GSTRIDE  ((PMAX + 1) * 3)   // float4s per tile in g_gauss (+1 dummy)

// ---------------- device scratch (static, no allocs; zero-init at load) ----
__device__ int                 g_hist32[NBUCKET];     // 4x8-bit per-tile counts
__device__ unsigned            g_mb[NMAX];            // (mask<<16) | bucket
__device__ int                 g_bcount[NT * NBUCKET];// per-tile prefix / slot ctr
__device__ int                 g_cutoff[NT];
__device__ int                 g_nvalid[NT];
__device__ unsigned long long  g_cand[NT * CANDMAX];
__device__ float4              g_gauss[NT * GSTRIDE];

// ---------------- kernel 1: rect/mask/bucket + packed histogram ------------
__global__ void k_prep(const float2* __restrict__ means,
                       const float4* __restrict__ cov,
                       const float* __restrict__ depths, int N) {
    int i = blockIdx.x * blockDim.x + threadIdx.x;
    if (i >= N) return;
    float4 cv = cov[i];
    float a = cv.x, b = cv.y, c = cv.z, d = cv.w;
    float det = a * d - b * c;
    float mid = 0.5f * (a + d);
    float s   = sqrtf(fmaxf(mid * mid - det, 0.1f));
    float rad = 3.0f * ceilf(sqrtf(fmaxf(mid + s, mid - s)));
    float2 mn = means[i];
    float xmin = fminf(fmaxf(mn.x - rad, 0.f), (float)(IMG_W - 1));
    float xmax = fminf(fmaxf(mn.x + rad, 0.f), (float)(IMG_W - 1));
    float ymin = fminf(fmaxf(mn.y - rad, 0.f), (float)(IMG_H - 1));
    float ymax = fminf(fmaxf(mn.y + rad, 0.f), (float)(IMG_H - 1));
    float dep = depths[i];
    int bucket = min(NBUCKET - 1, max(0, (int)(dep * 1600.0f)));
    unsigned mask = 0, e = 0;
#pragma unroll
    for (int ty = 0; ty < 2; ty++) {
        float hmin = (float)(ty * TSZ), hmax = hmin + (float)(TSZ - 1);
        bool ovy = fminf(ymax, hmax) > fmaxf(ymin, hmin);
#pragma unroll
        for (int tx = 0; tx < 2; tx++) {
            float wmin = (float)(tx * TSZ), wmax = wmin + (float)(TSZ - 1);
            bool ovx = fminf(xmax, wmax) > fmaxf(xmin, wmin);
            if (ovx && ovy) {
                int t = ty * 2 + tx;
                mask |= 1u << t;
                e += 1u << (8 * t);
            }
        }
    }
    if (e) atomicAdd(&g_hist32[bucket], (int)e);
    g_mb[i] = (mask << 16) | (unsigned)bucket;
}

// ---------------- kernel 2: per-tile prefix scan + rank-2048 cutoff --------
// Reads its tile's byte of the packed histogram; breaks once running >= PMAX.
__global__ void k_scan() {
    int t = blockIdx.x;
    int* bc = g_bcount + t * NBUCKET;
    __shared__ int warpsum[8];
    __shared__ int s_running, s_cut, s_ctot;
    if (threadIdx.x == 0) { s_running = 0; s_cut = NBUCKET - 1; s_ctot = -1; }
    __syncthreads();
    int lane = threadIdx.x & 31, wid = threadIdx.x >> 5;
    for (int base = 0; base < NBUCKET; base += 256) {
        int i = base + threadIdx.x;
        int v = (g_hist32[i] >> (8 * t)) & 0xFF;
        int x = v;
#pragma unroll
        for (int o = 1; o < 32; o <<= 1) {
            int y = __shfl_up_sync(0xffffffffu, x, o);
            if (lane >= o) x += y;
        }
        if (lane == 31) warpsum[wid] = x;
        __syncthreads();
        if (threadIdx.x < 8) {
            int w = warpsum[threadIdx.x];
#pragma unroll
            for (int o = 1; o < 8; o <<= 1) {
                int y = __shfl_up_sync(0xffu, w, o);
                if ((int)threadIdx.x >= o) w += y;
            }
            warpsum[threadIdx.x] = w;
        }
        __syncthreads();
        int incl = x + (wid ? warpsum[wid - 1] : 0);
        int excl = incl - v;
        int run = s_running;
        int gE = run + excl, gI = run + incl;
        bc[i] = gE;                       // exclusive prefix (scatter base)
        if (gE < PMAX && gI >= PMAX) { s_cut = i; s_ctot = gI; }
        __syncthreads();
        if (threadIdx.x == 0) s_running = run + warpsum[7];
        __syncthreads();
        if (s_running >= PMAX) break;     // cutoff found: rest is dead weight
    }
    if (threadIdx.x == 0) {
        int ctot, cut;
        if (s_ctot < 0) { cut = NBUCKET - 1; ctot = s_running; }
        else            { cut = s_cut;       ctot = s_ctot;    }
        g_cutoff[t] = cut;
        g_nvalid[t] = min(PMAX, ctot);
    }
}

// ---------------- kernel 3: scatter candidates (bucket <= cutoff) ----------
__global__ void k_scatter(const float* __restrict__ depths, int N) {
    int i = blockIdx.x * blockDim.x + threadIdx.x;
    if (i >= N) return;
    unsigned mb = g_mb[i];
    int b = (int)(mb & 0xFFFFu);
    unsigned mask = mb >> 16;
    int c0 = __ldg(&g_cutoff[0]), c1 = __ldg(&g_cutoff[1]);
    int c2 = __ldg(&g_cutoff[2]), c3 = __ldg(&g_cutoff[3]);
    bool p0 = (mask & 1u) && b <= c0;
    bool p1 = (mask & 2u) && b <= c1;
    bool p2 = (mask & 4u) && b <= c2;
    bool p3 = (mask & 8u) && b <= c3;
    if (!(p0 | p1 | p2 | p3)) return;
    unsigned long long key =
        ((unsigned long long)__float_as_uint(__ldg(&depths[i])) << 32) | (unsigned)i;
    if (p0) { int s = atomicAdd(&g_bcount[0 * NBUCKET + b], 1); if (s < CANDMAX) g_cand[0 * CANDMAX + s] = key; }
    if (p1) { int s = atomicAdd(&g_bcount[1 * NBUCKET + b], 1); if (s < CANDMAX) g_cand[1 * CANDMAX + s] = key; }
    if (p2) { int s = atomicAdd(&g_bcount[2 * NBUCKET + b], 1); if (s < CANDMAX) g_cand[2 * CANDMAX + s] = key; }
    if (p3) { int s = atomicAdd(&g_bcount[3 * NBUCKET + b], 1); if (s < CANDMAX) g_cand[3 * CANDMAX + s] = key; }
}

// ---------------- kernel 4: per-bucket sort + gather/pack (fused) ----------
__global__ void __launch_bounds__(1024) k_sortgather(
        const float2* __restrict__ means, const float4* __restrict__ cov,
        const float* __restrict__ color, const float* __restrict__ opac) {
    int t = blockIdx.x;
    int cut = g_cutoff[t];
    unsigned long long* A = g_cand + t * CANDMAX;
    const int* bc = g_bcount + t * NBUCKET;
    for (int b = threadIdx.x; b <= cut; b += 1024) {
        int start = b ? bc[b - 1] : 0;
        int end = min(bc[b], CANDMAX);
        for (int i = start + 1; i < end; i++) {
            unsigned long long key = A[i];
            int j = i - 1;
            while (j >= start && A[j] > key) { A[j + 1] = A[j]; j--; }
            A[j + 1] = key;
        }
    }
    __syncthreads();
    int nv = g_nvalid[t];
    float4* out = g_gauss + t * GSTRIDE;
    const float S = -0.7213475204444817f;      // -0.5 * log2(e)
    for (int s = threadIdx.x; s <= PMAX; s += 1024) {
        if (s == PMAX) {                       // neutral dummy (op = 0)
            out[3 * PMAX + 0] = make_float4(0.f, 0.f, 0.f, 0.f);
            out[3 * PMAX + 1] = make_float4(0.f, 0.f, -1000.f, 0.f);
            out[3 * PMAX + 2] = make_float4(0.f, 0.f, 0.f, 0.f);
        } else if (s < nv) {
            unsigned long long key = A[s];
            int gi = (int)(unsigned)(key & 0xFFFFFFFFull);
            float dep = __uint_as_float((unsigned)(key >> 32));
            float4 cv = cov[gi];
            float invdet = 1.0f / fmaxf(cv.x * cv.w - cv.y * cv.z, 1e-6f);
            float c00s = S * cv.w * invdet;
            float c11s = S * cv.x * invdet;
            float c01s = -S * (cv.y + cv.z) * invdet;
            float op = opac[gi];
            float2 mn = means[gi];
            out[3 * s + 0] = make_float4(-mn.x, -mn.y, c00s, c11s);
            out[3 * s + 1] = make_float4(c01s, op, __log2f(fmaxf(op, 1e-38f)), 0.f);
            out[3 * s + 2] = make_float4(color[3 * gi], color[3 * gi + 1],
                                         color[3 * gi + 2], dep);
        }
    }
}

// ---------------- kernel 5: fused cull + composite, 4 warps per bin --------
// CTA = one 8x4-pixel bin, 4 warps. Each warp composites a contiguous quarter
// of the depth-sorted candidate range (own cull + own local early exit on
// T_w < 1e-5); segments merge exactly via (T,C)∘(T',C') = (T·T', C + T·C').
// Also re-zeroes g_hist32 for the next graph replay (all readers precede us).
__global__ void __launch_bounds__(128) k_composite(float* __restrict__ out) {
    __shared__ __align__(16) unsigned short sbuf[4][64];
    __shared__ float sT[4][32];
    __shared__ float sC[4][32][5];

    int gtid = blockIdx.x * 128 + threadIdx.x;
    if (gtid < NBUCKET) g_hist32[gtid] = 0;    // prep for next replay

    int wid = threadIdx.x >> 5, lane = threadIdx.x & 31;
    int t = blockIdx.x >> 7, b = blockIdx.x & 127;
    int bx = b & 7, by = b >> 3;
    int px = (t & 1) * TSZ + bx * 8 + (lane & 7);
    int py = (t >> 1) * TSZ + by * 4 + (lane >> 3);
    float pxf = (float)px, pyf = (float)py;
    float x0 = (float)((t & 1) * TSZ + bx * 8), x1 = x0 + 7.f;
    float y0 = (float)((t >> 1) * TSZ + by * 4), y1 = y0 + 3.f;

    int nv = g_nvalid[t];
    const float4* gd = g_gauss + t * GSTRIDE;

    // this warp's contiguous quarter
    int nvq = (nv + 3) >> 2;
    int w0 = min(nv, wid * nvq);
    int w1 = min(nv, w0 + nvq);

    float T = 1.f, aR = 0.f, aG = 0.f, aB = 0.f, aD = 0.f, aA = 0.f;
    int head = 0, tail = 0;

    for (int base = w0; base < w1; base += 32) {
        int g = base + lane;
        bool keep = false;
        if (g < w1) {
            float4 q0 = __ldg(gd + 3 * g);
            float4 q1 = __ldg(gd + 3 * g + 1);
            float ax = x0 + q0.x, bxx = x1 + q0.x;   // dx interval
            float ay = y0 + q0.y, byy = y1 + q0.y;   // dy interval
            float msx = (ax <= 0.f && bxx >= 0.f) ? 0.f : fminf(ax * ax, bxx * bxx);
            float msy = (ay <= 0.f && byy >= 0.f) ? 0.f : fminf(ay * ay, byy * byy);
            float p1 = ax * ay, p2 = ax * byy, p3 = bxx * ay, p4 = bxx * byy;
            float pmax = fmaxf(fmaxf(p1, p2), fmaxf(p3, p4));
            float pmin = fminf(fminf(p1, p2), fminf(p3, p4));
            float cross = q1.x * ((q1.x > 0.f) ? pmax : pmin);
            float bound = q0.z * msx + q0.w * msy + cross + q1.z;
            keep = bound > -27.f;
        }
        unsigned bal = __ballot_sync(0xffffffffu, keep);
        int pos = head + __popc(bal & ((1u << lane) - 1u));
        if (keep) sbuf[wid][pos & 63] = (unsigned short)g;
        head += __popc(bal);
        __syncwarp();
        while (head - tail >= 4) {
            ushort4 i4 = *reinterpret_cast<const ushort4*>(&sbuf[wid][tail & 63]);
            tail += 4;
#pragma unroll
            for (int u = 0; u < 4; ++u) {
                int idx = (u == 0) ? i4.x : (u == 1) ? i4.y : (u == 2) ? i4.z : i4.w;
                float4 q0 = __ldg(gd + 3 * idx);
                float4 q1 = __ldg(gd + 3 * idx + 1);
                float4 q2 = __ldg(gd + 3 * idx + 2);
                float dx = pxf + q0.x, dy = pyf + q0.y;
                float e = exp2f(fmaf(dx * dy, q1.x, fmaf(dy * dy, q0.w, dx * dx * q0.z)));
                float alpha = fminf(e * q1.y, 0.99f);
                float w = alpha * T;
                aR = fmaf(w, q2.x, aR);
                aG = fmaf(w, q2.y, aG);
                aB = fmaf(w, q2.z, aB);
                aD = fmaf(w, q2.w, aD);
                aA += w;
                T -= w;                              // T *= (1 - alpha) exactly
            }
        }
        if (__all_sync(0xffffffffu, T < 1e-5f)) { tail = head; break; }
    }
    // flush remainder (pad ring with dummy PMAX entries to a multiple of 4)
    if (head - tail) {
        int pad = (4 - ((head - tail) & 3)) & 3;
        if (lane < pad) sbuf[wid][(head + lane) & 63] = (unsigned short)PMAX;
        head += pad;
        __syncwarp();
        while (head - tail >= 4) {
            ushort4 i4 = *reinterpret_cast<const ushort4*>(&sbuf[wid][tail & 63]);
            tail += 4;
#pragma unroll
            for (int u = 0; u < 4; ++u) {
                int idx = (u == 0) ? i4.x : (u == 1) ? i4.y : (u == 2) ? i4.z : i4.w;
                float4 q0 = __ldg(gd + 3 * idx);
                float4 q1 = __ldg(gd + 3 * idx + 1);
                float4 q2 = __ldg(gd + 3 * idx + 2);
                float dx = pxf + q0.x, dy = pyf + q0.y;
                float e = exp2f(fmaf(dx * dy, q1.x, fmaf(dy * dy, q0.w, dx * dx * q0.z)));
                float alpha = fminf(e * q1.y, 0.99f);
                float w = alpha * T;
                aR = fmaf(w, q2.x, aR);
                aG = fmaf(w, q2.y, aG);
                aB = fmaf(w, q2.z, aB);
                aD = fmaf(w, q2.w, aD);
                aA += w;
                T -= w;
            }
        }
    }

    // publish segment partials
    sT[wid][lane] = T;
    sC[wid][lane][0] = aR; sC[wid][lane][1] = aG; sC[wid][lane][2] = aB;
    sC[wid][lane][3] = aD; sC[wid][lane][4] = aA;
    __syncthreads();

    // warp 0: front-to-back merge of the 4 segments (exact), write output
    if (wid == 0) {
        float Tm = 1.f, R = 0.f, G = 0.f, B = 0.f, D = 0.f, A = 0.f;
#pragma unroll
        for (int w = 0; w < 4; ++w) {
            R = fmaf(Tm, sC[w][lane][0], R);
            G = fmaf(Tm, sC[w][lane][1], G);
            B = fmaf(Tm, sC[w][lane][2], B);
            D = fmaf(Tm, sC[w][lane][3], D);
            A = fmaf(Tm, sC[w][lane][4], A);
            Tm *= sT[w][lane];
        }
        int pix = py * IMG_W + px;
        float bg = 1.f - A;
        out[pix * 3 + 0] = R + bg;
        out[pix * 3 + 1] = G + bg;
        out[pix * 3 + 2] = B + bg;
        out[IMG_W * IMG_H * 3 + pix] = D;
        out[IMG_W * IMG_H * 4 + pix] = A;
    }
}

// ---------------- launch ----------------
extern "C" void kernel_launch(void* const* d_in, const int* in_sizes, int n_in,
                              void* d_out, int out_size) {
    const float* means  = (const float*)d_in[0];
    const float* cov    = (const float*)d_in[1];
    const float* color  = (const float*)d_in[2];
    const float* opac   = (const float*)d_in[3];
    const float* depths = (const float*)d_in[4];
    int N = in_sizes[4];

    k_prep<<<(N + 255) / 256, 256>>>((const float2*)means, (const float4*)cov, depths, N);
    k_scan<<<NT, 256>>>();
    k_scatter<<<(N + 255) / 256, 256>>>(depths, N);
    k_sortgather<<<NT, 1024>>>((const float2*)means, (const float4*)cov, color, opac);
    k_composite<<<NT * BINS, 128>>>((float*)d_out);
}

// round 11
// speedup vs baseline: 15.9516x; 1.3118x over previous
#include <cuda_runtime.h>
#include <stdint.h>

// ---------------- constants ----------------
#define NMAX     131072
#define NBUCKET  16384
#define NT       4          // 2x2 tiles
#define PMAX     2048
#define CANDMAX  4096
#define IMG_W    128
#define IMG_H    128
#define TSZ      64
#define BINS     128        // per tile: 8 x-bins (8px) x 16 y-bins (4px)
#define GSTRIDE  ((PMAX + 1) * 3)   // float4s per tile in g_gauss (+1 dummy)

// ---------------- device scratch (static, no allocs; zero-init at load) ----
__device__ int                 g_hist32[NBUCKET];     // 4x8-bit per-tile counts
__device__ unsigned            g_mb[NMAX];            // (mask<<16) | bucket
__device__ int                 g_bcount[NT * NBUCKET];// per-tile prefix / slot ctr
__device__ int                 g_cutoff[NT];
__device__ int                 g_nvalid[NT];
__device__ unsigned long long  g_cand[NT * CANDMAX];
__device__ float4              g_gauss[NT * GSTRIDE];

// ---------------- kernel 1: rect/mask/bucket + packed histogram ------------
__global__ void k_prep(const float2* __restrict__ means,
                       const float4* __restrict__ cov,
                       const float* __restrict__ depths, int N) {
    int i = blockIdx.x * blockDim.x + threadIdx.x;
    if (i >= N) return;
    float4 cv = cov[i];
    float a = cv.x, b = cv.y, c = cv.z, d = cv.w;
    float det = a * d - b * c;
    float mid = 0.5f * (a + d);
    float s   = sqrtf(fmaxf(mid * mid - det, 0.1f));
    float rad = 3.0f * ceilf(sqrtf(fmaxf(mid + s, mid - s)));
    float2 mn = means[i];
    float xmin = fminf(fmaxf(mn.x - rad, 0.f), (float)(IMG_W - 1));
    float xmax = fminf(fmaxf(mn.x + rad, 0.f), (float)(IMG_W - 1));
    float ymin = fminf(fmaxf(mn.y - rad, 0.f), (float)(IMG_H - 1));
    float ymax = fminf(fmaxf(mn.y + rad, 0.f), (float)(IMG_H - 1));
    float dep = depths[i];
    int bucket = min(NBUCKET - 1, max(0, (int)(dep * 1600.0f)));
    unsigned mask = 0, e = 0;
#pragma unroll
    for (int ty = 0; ty < 2; ty++) {
        float hmin = (float)(ty * TSZ), hmax = hmin + (float)(TSZ - 1);
        bool ovy = fminf(ymax, hmax) > fmaxf(ymin, hmin);
#pragma unroll
        for (int tx = 0; tx < 2; tx++) {
            float wmin = (float)(tx * TSZ), wmax = wmin + (float)(TSZ - 1);
            bool ovx = fminf(xmax, wmax) > fmaxf(xmin, wmin);
            if (ovx && ovy) {
                int t = ty * 2 + tx;
                mask |= 1u << t;
                e += 1u << (8 * t);
            }
        }
    }
    if (e) atomicAdd(&g_hist32[bucket], (int)e);
    g_mb[i] = (mask << 16) | (unsigned)bucket;
}

// ---------------- kernel 2: per-tile prefix scan + rank-2048 cutoff --------
__global__ void k_scan() {
    int t = blockIdx.x;
    int* bc = g_bcount + t * NBUCKET;
    __shared__ int warpsum[8];
    __shared__ int s_running, s_cut, s_ctot;
    if (threadIdx.x == 0) { s_running = 0; s_cut = NBUCKET - 1; s_ctot = -1; }
    __syncthreads();
    int lane = threadIdx.x & 31, wid = threadIdx.x >> 5;
    for (int base = 0; base < NBUCKET; base += 256) {
        int i = base + threadIdx.x;
        int v = (g_hist32[i] >> (8 * t)) & 0xFF;
        int x = v;
#pragma unroll
        for (int o = 1; o < 32; o <<= 1) {
            int y = __shfl_up_sync(0xffffffffu, x, o);
            if (lane >= o) x += y;
        }
        if (lane == 31) warpsum[wid] = x;
        __syncthreads();
        if (threadIdx.x < 8) {
            int w = warpsum[threadIdx.x];
#pragma unroll
            for (int o = 1; o < 8; o <<= 1) {
                int y = __shfl_up_sync(0xffu, w, o);
                if ((int)threadIdx.x >= o) w += y;
            }
            warpsum[threadIdx.x] = w;
        }
        __syncthreads();
        int incl = x + (wid ? warpsum[wid - 1] : 0);
        int excl = incl - v;
        int run = s_running;
        int gE = run + excl, gI = run + incl;
        bc[i] = gE;                       // exclusive prefix (scatter base)
        if (gE < PMAX && gI >= PMAX) { s_cut = i; s_ctot = gI; }
        __syncthreads();
        if (threadIdx.x == 0) s_running = run + warpsum[7];
        __syncthreads();
        if (s_running >= PMAX) break;     // cutoff found: rest is dead weight
    }
    if (threadIdx.x == 0) {
        int ctot, cut;
        if (s_ctot < 0) { cut = NBUCKET - 1; ctot = s_running; }
        else            { cut = s_cut;       ctot = s_ctot;    }
        g_cutoff[t] = cut;
        g_nvalid[t] = min(PMAX, ctot);
    }
}

// ---------------- kernel 3: scatter candidates (bucket <= cutoff) ----------
__global__ void k_scatter(const float* __restrict__ depths, int N) {
    int i = blockIdx.x * blockDim.x + threadIdx.x;
    if (i >= N) return;
    unsigned mb = g_mb[i];
    int b = (int)(mb & 0xFFFFu);
    unsigned mask = mb >> 16;
    int c0 = __ldg(&g_cutoff[0]), c1 = __ldg(&g_cutoff[1]);
    int c2 = __ldg(&g_cutoff[2]), c3 = __ldg(&g_cutoff[3]);
    bool p0 = (mask & 1u) && b <= c0;
    bool p1 = (mask & 2u) && b <= c1;
    bool p2 = (mask & 4u) && b <= c2;
    bool p3 = (mask & 8u) && b <= c3;
    if (!(p0 | p1 | p2 | p3)) return;
    unsigned long long key =
        ((unsigned long long)__float_as_uint(__ldg(&depths[i])) << 32) | (unsigned)i;
    if (p0) { int s = atomicAdd(&g_bcount[0 * NBUCKET + b], 1); if (s < CANDMAX) g_cand[0 * CANDMAX + s] = key; }
    if (p1) { int s = atomicAdd(&g_bcount[1 * NBUCKET + b], 1); if (s < CANDMAX) g_cand[1 * CANDMAX + s] = key; }
    if (p2) { int s = atomicAdd(&g_bcount[2 * NBUCKET + b], 1); if (s < CANDMAX) g_cand[2 * CANDMAX + s] = key; }
    if (p3) { int s = atomicAdd(&g_bcount[3 * NBUCKET + b], 1); if (s < CANDMAX) g_cand[3 * CANDMAX + s] = key; }
}

// ---------------- kernel 4: parallel rank + gather/pack --------------------
// One thread per candidate. After scatter, g_bcount[b] = inclusive prefix, so
// bucket b spans [bc[b-1], bc[b]). Final sorted position of a key = bucket
// start + (# keys in its bucket strictly smaller). Keys are unique (index in
// low bits) => exact, bit-identical to the stable global argsort. Fully
// parallel: no serial chains, 64 CTAs instead of 4.
__global__ void k_rankgather(
        const float2* __restrict__ means, const float4* __restrict__ cov,
        const float* __restrict__ color, const float* __restrict__ opac) {
    int t = blockIdx.y;
    int s = blockIdx.x * 256 + threadIdx.x;
    float4* out = g_gauss + t * GSTRIDE;
    if (blockIdx.x == 0 && threadIdx.x == 0) {   // neutral dummy (op = 0)
        out[3 * PMAX + 0] = make_float4(0.f, 0.f, 0.f, 0.f);
        out[3 * PMAX + 1] = make_float4(0.f, 0.f, -1000.f, 0.f);
        out[3 * PMAX + 2] = make_float4(0.f, 0.f, 0.f, 0.f);
    }
    const int* bc = g_bcount + t * NBUCKET;
    int cut = __ldg(&g_cutoff[t]);
    int ctot = min(__ldg(&bc[cut]), CANDMAX);
    if (s >= ctot) return;
    const unsigned long long* A = g_cand + t * CANDMAX;
    unsigned long long key = __ldg(&A[s]);
    float dep = __uint_as_float((unsigned)(key >> 32));
    int b = min(NBUCKET - 1, max(0, (int)(dep * 1600.0f)));  // == prep's bucket
    int start = b ? __ldg(&bc[b - 1]) : 0;
    int end = min(__ldg(&bc[b]), CANDMAX);
    int rank = 0;
    for (int j = start; j < end; ++j) rank += (__ldg(&A[j]) < key);
    int pos = start + rank;
    if (pos >= PMAX) return;                     // beyond front-most 2048
    int gi = (int)(unsigned)(key & 0xFFFFFFFFull);
    float4 cv = cov[gi];
    float invdet = 1.0f / fmaxf(cv.x * cv.w - cv.y * cv.z, 1e-6f);
    const float S = -0.7213475204444817f;        // -0.5 * log2(e)
    float c00s = S * cv.w * invdet;
    float c11s = S * cv.x * invdet;
    float c01s = -S * (cv.y + cv.z) * invdet;
    float op = opac[gi];
    float2 mn = means[gi];
    out[3 * pos + 0] = make_float4(-mn.x, -mn.y, c00s, c11s);
    out[3 * pos + 1] = make_float4(c01s, op, __log2f(fmaxf(op, 1e-38f)), 0.f);
    out[3 * pos + 2] = make_float4(color[3 * gi], color[3 * gi + 1],
                                   color[3 * gi + 2], dep);
}

// ---------------- kernel 5: fused cull + composite, 4 warps per bin --------
// CTA = one 8x4-pixel bin, 4 warps. Each warp composites a contiguous quarter
// of the depth-sorted candidate range (own cull + own local early exit on
// T_w < 1e-5); segments merge exactly via (T,C)∘(T',C') = (T·T', C + T·C').
// Also re-zeroes g_hist32 for the next graph replay (all readers precede us).
__global__ void __launch_bounds__(128) k_composite(float* __restrict__ out) {
    __shared__ __align__(16) unsigned short sbuf[4][64];
    __shared__ float sT[4][32];
    __shared__ float sC[4][32][5];

    int gtid = blockIdx.x * 128 + threadIdx.x;
    if (gtid < NBUCKET) g_hist32[gtid] = 0;    // prep for next replay

    int wid = threadIdx.x >> 5, lane = threadIdx.x & 31;
    int t = blockIdx.x >> 7, b = blockIdx.x & 127;
    int bx = b & 7, by = b >> 3;
    int px = (t & 1) * TSZ + bx * 8 + (lane & 7);
    int py = (t >> 1) * TSZ + by * 4 + (lane >> 3);
    float pxf = (float)px, pyf = (float)py;
    float x0 = (float)((t & 1) * TSZ + bx * 8), x1 = x0 + 7.f;
    float y0 = (float)((t >> 1) * TSZ + by * 4), y1 = y0 + 3.f;

    int nv = g_nvalid[t];
    const float4* gd = g_gauss + t * GSTRIDE;

    // this warp's contiguous quarter
    int nvq = (nv + 3) >> 2;
    int w0 = min(nv, wid * nvq);
    int w1 = min(nv, w0 + nvq);

    float T = 1.f, aR = 0.f, aG = 0.f, aB = 0.f, aD = 0.f, aA = 0.f;
    int head = 0, tail = 0;

    for (int base = w0; base < w1; base += 32) {
        int g = base + lane;
        bool keep = false;
        if (g < w1) {
            float4 q0 = __ldg(gd + 3 * g);
            float4 q1 = __ldg(gd + 3 * g + 1);
            float ax = x0 + q0.x, bxx = x1 + q0.x;   // dx interval
            float ay = y0 + q0.y, byy = y1 + q0.y;   // dy interval
            float msx = (ax <= 0.f && bxx >= 0.f) ? 0.f : fminf(ax * ax, bxx * bxx);
            float msy = (ay <= 0.f && byy >= 0.f) ? 0.f : fminf(ay * ay, byy * byy);
            float p1 = ax * ay, p2 = ax * byy, p3 = bxx * ay, p4 = bxx * byy;
            float pmax = fmaxf(fmaxf(p1, p2), fmaxf(p3, p4));
            float pmin = fminf(fminf(p1, p2), fminf(p3, p4));
            float cross = q1.x * ((q1.x > 0.f) ? pmax : pmin);
            float bound = q0.z * msx + q0.w * msy + cross + q1.z;
            keep = bound > -27.f;
        }
        unsigned bal = __ballot_sync(0xffffffffu, keep);
        int pos = head + __popc(bal & ((1u << lane) - 1u));
        if (keep) sbuf[wid][pos & 63] = (unsigned short)g;
        head += __popc(bal);
        __syncwarp();
        while (head - tail >= 4) {
            ushort4 i4 = *reinterpret_cast<const ushort4*>(&sbuf[wid][tail & 63]);
            tail += 4;
#pragma unroll
            for (int u = 0; u < 4; ++u) {
                int idx = (u == 0) ? i4.x : (u == 1) ? i4.y : (u == 2) ? i4.z : i4.w;
                float4 q0 = __ldg(gd + 3 * idx);
                float4 q1 = __ldg(gd + 3 * idx + 1);
                float4 q2 = __ldg(gd + 3 * idx + 2);
                float dx = pxf + q0.x, dy = pyf + q0.y;
                float e = exp2f(fmaf(dx * dy, q1.x, fmaf(dy * dy, q0.w, dx * dx * q0.z)));
                float alpha = fminf(e * q1.y, 0.99f);
                float w = alpha * T;
                aR = fmaf(w, q2.x, aR);
                aG = fmaf(w, q2.y, aG);
                aB = fmaf(w, q2.z, aB);
                aD = fmaf(w, q2.w, aD);
                aA += w;
                T -= w;                              // T *= (1 - alpha) exactly
            }
        }
        if (__all_sync(0xffffffffu, T < 1e-5f)) { tail = head; break; }
    }
    // flush remainder (pad ring with dummy PMAX entries to a multiple of 4)
    if (head - tail) {
        int pad = (4 - ((head - tail) & 3)) & 3;
        if (lane < pad) sbuf[wid][(head + lane) & 63] = (unsigned short)PMAX;
        head += pad;
        __syncwarp();
        while (head - tail >= 4) {
            ushort4 i4 = *reinterpret_cast<const ushort4*>(&sbuf[wid][tail & 63]);
            tail += 4;
#pragma unroll
            for (int u = 0; u < 4; ++u) {
                int idx = (u == 0) ? i4.x : (u == 1) ? i4.y : (u == 2) ? i4.z : i4.w;
                float4 q0 = __ldg(gd + 3 * idx);
                float4 q1 = __ldg(gd + 3 * idx + 1);
                float4 q2 = __ldg(gd + 3 * idx + 2);
                float dx = pxf + q0.x, dy = pyf + q0.y;
                float e = exp2f(fmaf(dx * dy, q1.x, fmaf(dy * dy, q0.w, dx * dx * q0.z)));
                float alpha = fminf(e * q1.y, 0.99f);
                float w = alpha * T;
                aR = fmaf(w, q2.x, aR);
                aG = fmaf(w, q2.y, aG);
                aB = fmaf(w, q2.z, aB);
                aD = fmaf(w, q2.w, aD);
                aA += w;
                T -= w;
            }
        }
    }

    // publish segment partials
    sT[wid][lane] = T;
    sC[wid][lane][0] = aR; sC[wid][lane][1] = aG; sC[wid][lane][2] = aB;
    sC[wid][lane][3] = aD; sC[wid][lane][4] = aA;
    __syncthreads();

    // warp 0: front-to-back merge of the 4 segments (exact), write output
    if (wid == 0) {
        float Tm = 1.f, R = 0.f, G = 0.f, B = 0.f, D = 0.f, A = 0.f;
#pragma unroll
        for (int w = 0; w < 4; ++w) {
            R = fmaf(Tm, sC[w][lane][0], R);
            G = fmaf(Tm, sC[w][lane][1], G);
            B = fmaf(Tm, sC[w][lane][2], B);
            D = fmaf(Tm, sC[w][lane][3], D);
            A = fmaf(Tm, sC[w][lane][4], A);
            Tm *= sT[w][lane];
        }
        int pix = py * IMG_W + px;
        float bg = 1.f - A;
        out[pix * 3 + 0] = R + bg;
        out[pix * 3 + 1] = G + bg;
        out[pix * 3 + 2] = B + bg;
        out[IMG_W * IMG_H * 3 + pix] = D;
        out[IMG_W * IMG_H * 4 + pix] = A;
    }
}

// ---------------- launch ----------------
extern "C" void kernel_launch(void* const* d_in, const int* in_sizes, int n_in,
                              void* d_out, int out_size) {
    const float* means  = (const float*)d_in[0];
    const float* cov    = (const float*)d_in[1];
    const float* color  = (const float*)d_in[2];
    const float* opac   = (const float*)d_in[3];
    const float* depths = (const float*)d_in[4];
    int N = in_sizes[4];

    k_prep<<<(N + 255) / 256, 256>>>((const float2*)means, (const float4*)cov, depths, N);
    k_scan<<<NT, 256>>>();
    k_scatter<<<(N + 255) / 256, 256>>>(depths, N);
    dim3 rg((CANDMAX + 255) / 256, NT);
    k_rankgather<<<rg, 256>>>((const float2*)means, (const float4*)cov, color, opac);
    k_composite<<<NT * BINS, 128>>>((float*)d_out);
}

// round 12
// speedup vs baseline: 17.0063x; 1.0661x over previous
#include <cuda_runtime.h>
#include <stdint.h>

// ---------------- constants ----------------
#define NMAX     131072
#define NBUCKET  16384
#define NT       4          // 2x2 tiles
#define PMAX     2048
#define CANDMAX  4096
#define IMG_W    128
#define IMG_H    128
#define TSZ      64
#define BINS     128        // per tile: 8 x-bins (8px) x 16 y-bins (4px)
#define NSEG     8          // warps (segments) per bin in composite
#define GSTRIDE  ((PMAX + 1) * 3)   // float4s per tile in g_gauss (+1 dummy)

// ---------------- device scratch (static, no allocs; zero-init at load) ----
__device__ int                 g_hist32[NBUCKET];     // 4x8-bit per-tile counts
__device__ unsigned            g_mb[NMAX];            // (mask<<16) | bucket
__device__ int                 g_bcount[NT * NBUCKET];// per-tile prefix / slot ctr
__device__ int                 g_cutoff[NT];
__device__ int                 g_nvalid[NT];
__device__ unsigned long long  g_cand[NT * CANDMAX];
__device__ float4              g_gauss[NT * GSTRIDE];

// ---------------- kernel 1: rect/mask/bucket + packed histogram ------------
__global__ void k_prep(const float2* __restrict__ means,
                       const float4* __restrict__ cov,
                       const float* __restrict__ depths, int N) {
    int i = blockIdx.x * blockDim.x + threadIdx.x;
    if (i >= N) return;
    float4 cv = cov[i];
    float a = cv.x, b = cv.y, c = cv.z, d = cv.w;
    float det = a * d - b * c;
    float mid = 0.5f * (a + d);
    float s   = sqrtf(fmaxf(mid * mid - det, 0.1f));
    float rad = 3.0f * ceilf(sqrtf(fmaxf(mid + s, mid - s)));
    float2 mn = means[i];
    float xmin = fminf(fmaxf(mn.x - rad, 0.f), (float)(IMG_W - 1));
    float xmax = fminf(fmaxf(mn.x + rad, 0.f), (float)(IMG_W - 1));
    float ymin = fminf(fmaxf(mn.y - rad, 0.f), (float)(IMG_H - 1));
    float ymax = fminf(fmaxf(mn.y + rad, 0.f), (float)(IMG_H - 1));
    float dep = depths[i];
    int bucket = min(NBUCKET - 1, max(0, (int)(dep * 1600.0f)));
    unsigned mask = 0, e = 0;
#pragma unroll
    for (int ty = 0; ty < 2; ty++) {
        float hmin = (float)(ty * TSZ), hmax = hmin + (float)(TSZ - 1);
        bool ovy = fminf(ymax, hmax) > fmaxf(ymin, hmin);
#pragma unroll
        for (int tx = 0; tx < 2; tx++) {
            float wmin = (float)(tx * TSZ), wmax = wmin + (float)(TSZ - 1);
            bool ovx = fminf(xmax, wmax) > fmaxf(xmin, wmin);
            if (ovx && ovy) {
                int t = ty * 2 + tx;
                mask |= 1u << t;
                e += 1u << (8 * t);
            }
        }
    }
    if (e) atomicAdd(&g_hist32[bucket], (int)e);
    g_mb[i] = (mask << 16) | (unsigned)bucket;
}

// ---------------- kernel 2: per-tile prefix scan + rank-2048 cutoff --------
__global__ void k_scan() {
    int t = blockIdx.x;
    int* bc = g_bcount + t * NBUCKET;
    __shared__ int warpsum[8];
    __shared__ int s_running, s_cut, s_ctot;
    if (threadIdx.x == 0) { s_running = 0; s_cut = NBUCKET - 1; s_ctot = -1; }
    __syncthreads();
    int lane = threadIdx.x & 31, wid = threadIdx.x >> 5;
    for (int base = 0; base < NBUCKET; base += 256) {
        int i = base + threadIdx.x;
        int v = (g_hist32[i] >> (8 * t)) & 0xFF;
        int x = v;
#pragma unroll
        for (int o = 1; o < 32; o <<= 1) {
            int y = __shfl_up_sync(0xffffffffu, x, o);
            if (lane >= o) x += y;
        }
        if (lane == 31) warpsum[wid] = x;
        __syncthreads();
        if (threadIdx.x < 8) {
            int w = warpsum[threadIdx.x];
#pragma unroll
            for (int o = 1; o < 8; o <<= 1) {
                int y = __shfl_up_sync(0xffu, w, o);
                if ((int)threadIdx.x >= o) w += y;
            }
            warpsum[threadIdx.x] = w;
        }
        __syncthreads();
        int incl = x + (wid ? warpsum[wid - 1] : 0);
        int excl = incl - v;
        int run = s_running;
        int gE = run + excl, gI = run + incl;
        bc[i] = gE;                       // exclusive prefix (scatter base)
        if (gE < PMAX && gI >= PMAX) { s_cut = i; s_ctot = gI; }
        __syncthreads();
        if (threadIdx.x == 0) s_running = run + warpsum[7];
        __syncthreads();
        if (s_running >= PMAX) break;     // cutoff found: rest is dead weight
    }
    if (threadIdx.x == 0) {
        int ctot, cut;
        if (s_ctot < 0) { cut = NBUCKET - 1; ctot = s_running; }
        else            { cut = s_cut;       ctot = s_ctot;    }
        g_cutoff[t] = cut;
        g_nvalid[t] = min(PMAX, ctot);
    }
}

// ---------------- kernel 3: scatter candidates (bucket <= cutoff) ----------
__global__ void k_scatter(const float* __restrict__ depths, int N) {
    int i = blockIdx.x * blockDim.x + threadIdx.x;
    if (i >= N) return;
    unsigned mb = g_mb[i];
    int b = (int)(mb & 0xFFFFu);
    unsigned mask = mb >> 16;
    int c0 = __ldg(&g_cutoff[0]), c1 = __ldg(&g_cutoff[1]);
    int c2 = __ldg(&g_cutoff[2]), c3 = __ldg(&g_cutoff[3]);
    bool p0 = (mask & 1u) && b <= c0;
    bool p1 = (mask & 2u) && b <= c1;
    bool p2 = (mask & 4u) && b <= c2;
    bool p3 = (mask & 8u) && b <= c3;
    if (!(p0 | p1 | p2 | p3)) return;
    unsigned long long key =
        ((unsigned long long)__float_as_uint(__ldg(&depths[i])) << 32) | (unsigned)i;
    if (p0) { int s = atomicAdd(&g_bcount[0 * NBUCKET + b], 1); if (s < CANDMAX) g_cand[0 * CANDMAX + s] = key; }
    if (p1) { int s = atomicAdd(&g_bcount[1 * NBUCKET + b], 1); if (s < CANDMAX) g_cand[1 * CANDMAX + s] = key; }
    if (p2) { int s = atomicAdd(&g_bcount[2 * NBUCKET + b], 1); if (s < CANDMAX) g_cand[2 * CANDMAX + s] = key; }
    if (p3) { int s = atomicAdd(&g_bcount[3 * NBUCKET + b], 1); if (s < CANDMAX) g_cand[3 * CANDMAX + s] = key; }
}

// ---------------- kernel 4: parallel rank + gather/pack --------------------
// One thread per candidate; gather-source loads issued BEFORE the rank loop so
// they overlap the bucket-bound reads (chain: key -> {gi loads || rank scan}).
// pos = bucket_start + |{smaller keys in bucket}| is bit-identical to the
// stable global argsort (keys unique: index in low 32 bits).
__global__ void k_rankgather(
        const float2* __restrict__ means, const float4* __restrict__ cov,
        const float* __restrict__ color, const float* __restrict__ opac) {
    int t = blockIdx.y;
    int s = blockIdx.x * 256 + threadIdx.x;
    float4* out = g_gauss + t * GSTRIDE;
    if (blockIdx.x == 0 && threadIdx.x == 0) {   // neutral dummy (op = 0)
        out[3 * PMAX + 0] = make_float4(0.f, 0.f, 0.f, 0.f);
        out[3 * PMAX + 1] = make_float4(0.f, 0.f, -1000.f, 0.f);
        out[3 * PMAX + 2] = make_float4(0.f, 0.f, 0.f, 0.f);
    }
    const int* bc = g_bcount + t * NBUCKET;
    int cut = __ldg(&g_cutoff[t]);
    int ctot = min(__ldg(&bc[cut]), CANDMAX);
    if (s >= ctot) return;
    const unsigned long long* A = g_cand + t * CANDMAX;
    unsigned long long key = __ldg(&A[s]);
    int gi = (int)(unsigned)(key & 0xFFFFFFFFull);
    // issue gather-source loads early (independent of rank computation)
    float4 cv = __ldg(&cov[gi]);
    float2 mn = __ldg(&means[gi]);
    float op = __ldg(&opac[gi]);
    float cr = __ldg(&color[3 * gi]);
    float cg = __ldg(&color[3 * gi + 1]);
    float cb = __ldg(&color[3 * gi + 2]);
    float dep = __uint_as_float((unsigned)(key >> 32));
    int b = min(NBUCKET - 1, max(0, (int)(dep * 1600.0f)));  // == prep's bucket
    int start = b ? __ldg(&bc[b - 1]) : 0;
    int end = min(__ldg(&bc[b]), CANDMAX);
    int rank = 0;
    for (int j = start; j < end; ++j) rank += (__ldg(&A[j]) < key);
    int pos = start + rank;
    if (pos >= PMAX) return;                     // beyond front-most 2048
    float invdet = 1.0f / fmaxf(cv.x * cv.w - cv.y * cv.z, 1e-6f);
    const float S = -0.7213475204444817f;        // -0.5 * log2(e)
    float c00s = S * cv.w * invdet;
    float c11s = S * cv.x * invdet;
    float c01s = -S * (cv.y + cv.z) * invdet;
    out[3 * pos + 0] = make_float4(-mn.x, -mn.y, c00s, c11s);
    out[3 * pos + 1] = make_float4(c01s, op, __log2f(fmaxf(op, 1e-38f)), 0.f);
    out[3 * pos + 2] = make_float4(cr, cg, cb, dep);
}

// ---------------- kernel 5: fused cull + composite, 8 warps per bin --------
// CTA = one 8x4-pixel bin, 8 warps. Each warp composites a contiguous eighth
// of the depth-sorted candidate range (own cull + own local early exit on
// T_w < 1e-5); segments merge exactly via (T,C)∘(T',C') = (T·T', C + T·C').
// Also re-zeroes g_hist32 for the next graph replay (all readers precede us).
__global__ void __launch_bounds__(32 * NSEG) k_composite(float* __restrict__ out) {
    __shared__ __align__(16) unsigned short sbuf[NSEG][64];
    __shared__ float sT[NSEG][32];
    __shared__ float sC[NSEG][32][5];

    int gtid = blockIdx.x * (32 * NSEG) + threadIdx.x;
    if (gtid < NBUCKET) g_hist32[gtid] = 0;    // prep for next replay

    int wid = threadIdx.x >> 5, lane = threadIdx.x & 31;
    int t = blockIdx.x >> 7, b = blockIdx.x & 127;
    int bx = b & 7, by = b >> 3;
    int px = (t & 1) * TSZ + bx * 8 + (lane & 7);
    int py = (t >> 1) * TSZ + by * 4 + (lane >> 3);
    float pxf = (float)px, pyf = (float)py;
    float x0 = (float)((t & 1) * TSZ + bx * 8), x1 = x0 + 7.f;
    float y0 = (float)((t >> 1) * TSZ + by * 4), y1 = y0 + 3.f;

    int nv = g_nvalid[t];
    const float4* gd = g_gauss + t * GSTRIDE;

    // this warp's contiguous segment
    int nvq = (nv + NSEG - 1) / NSEG;
    int w0 = min(nv, wid * nvq);
    int w1 = min(nv, w0 + nvq);

    float T = 1.f, aR = 0.f, aG = 0.f, aB = 0.f, aD = 0.f, aA = 0.f;
    int head = 0, tail = 0;

    for (int base = w0; base < w1; base += 32) {
        int g = base + lane;
        bool keep = false;
        if (g < w1) {
            float4 q0 = __ldg(gd + 3 * g);
            float4 q1 = __ldg(gd + 3 * g + 1);
            float ax = x0 + q0.x, bxx = x1 + q0.x;   // dx interval
            float ay = y0 + q0.y, byy = y1 + q0.y;   // dy interval
            float msx = (ax <= 0.f && bxx >= 0.f) ? 0.f : fminf(ax * ax, bxx * bxx);
            float msy = (ay <= 0.f && byy >= 0.f) ? 0.f : fminf(ay * ay, byy * byy);
            float p1 = ax * ay, p2 = ax * byy, p3 = bxx * ay, p4 = bxx * byy;
            float pmax = fmaxf(fmaxf(p1, p2), fmaxf(p3, p4));
            float pmin = fminf(fminf(p1, p2), fminf(p3, p4));
            float cross = q1.x * ((q1.x > 0.f) ? pmax : pmin);
            float bound = q0.z * msx + q0.w * msy + cross + q1.z;
            keep = bound > -27.f;
        }
        unsigned bal = __ballot_sync(0xffffffffu, keep);
        int pos = head + __popc(bal & ((1u << lane) - 1u));
        if (keep) sbuf[wid][pos & 63] = (unsigned short)g;
        head += __popc(bal);
        __syncwarp();
        while (head - tail >= 4) {
            ushort4 i4 = *reinterpret_cast<const ushort4*>(&sbuf[wid][tail & 63]);
            tail += 4;
#pragma unroll
            for (int u = 0; u < 4; ++u) {
                int idx = (u == 0) ? i4.x : (u == 1) ? i4.y : (u == 2) ? i4.z : i4.w;
                float4 q0 = __ldg(gd + 3 * idx);
                float4 q1 = __ldg(gd + 3 * idx + 1);
                float4 q2 = __ldg(gd + 3 * idx + 2);
                float dx = pxf + q0.x, dy = pyf + q0.y;
                float e = exp2f(fmaf(dx * dy, q1.x, fmaf(dy * dy, q0.w, dx * dx * q0.z)));
                float alpha = fminf(e * q1.y, 0.99f);
                float w = alpha * T;
                aR = fmaf(w, q2.x, aR);
                aG = fmaf(w, q2.y, aG);
                aB = fmaf(w, q2.z, aB);
                aD = fmaf(w, q2.w, aD);
                aA += w;
                T -= w;                              // T *= (1 - alpha) exactly
            }
        }
        if (__all_sync(0xffffffffu, T < 1e-5f)) { tail = head; break; }
    }
    // flush remainder (pad ring with dummy PMAX entries to a multiple of 4)
    if (head - tail) {
        int pad = (4 - ((head - tail) & 3)) & 3;
        if (lane < pad) sbuf[wid][(head + lane) & 63] = (unsigned short)PMAX;
        head += pad;
        __syncwarp();
        while (head - tail >= 4) {
            ushort4 i4 = *reinterpret_cast<const ushort4*>(&sbuf[wid][tail & 63]);
            tail += 4;
#pragma unroll
            for (int u = 0; u < 4; ++u) {
                int idx = (u == 0) ? i4.x : (u == 1) ? i4.y : (u == 2) ? i4.z : i4.w;
                float4 q0 = __ldg(gd + 3 * idx);
                float4 q1 = __ldg(gd + 3 * idx + 1);
                float4 q2 = __ldg(gd + 3 * idx + 2);
                float dx = pxf + q0.x, dy = pyf + q0.y;
                float e = exp2f(fmaf(dx * dy, q1.x, fmaf(dy * dy, q0.w, dx * dx * q0.z)));
                float alpha = fminf(e * q1.y, 0.99f);
                float w = alpha * T;
                aR = fmaf(w, q2.x, aR);
                aG = fmaf(w, q2.y, aG);
                aB = fmaf(w, q2.z, aB);
                aD = fmaf(w, q2.w, aD);
                aA += w;
                T -= w;
            }
        }
    }

    // publish segment partials
    sT[wid][lane] = T;
    sC[wid][lane][0] = aR; sC[wid][lane][1] = aG; sC[wid][lane][2] = aB;
    sC[wid][lane][3] = aD; sC[wid][lane][4] = aA;
    __syncthreads();

    // warp 0: front-to-back merge of the NSEG segments (exact), write output
    if (wid == 0) {
        float Tm = 1.f, R = 0.f, G = 0.f, B = 0.f, D = 0.f, A = 0.f;
#pragma unroll
        for (int w = 0; w < NSEG; ++w) {
            R = fmaf(Tm, sC[w][lane][0], R);
            G = fmaf(Tm, sC[w][lane][1], G);
            B = fmaf(Tm, sC[w][lane][2], B);
            D = fmaf(Tm, sC[w][lane][3], D);
            A = fmaf(Tm, sC[w][lane][4], A);
            Tm *= sT[w][lane];
        }
        int pix = py * IMG_W + px;
        float bg = 1.f - A;
        out[pix * 3 + 0] = R + bg;
        out[pix * 3 + 1] = G + bg;
        out[pix * 3 + 2] = B + bg;
        out[IMG_W * IMG_H * 3 + pix] = D;
        out[IMG_W * IMG_H * 4 + pix] = A;
    }
}

// ---------------- launch ----------------
extern "C" void kernel_launch(void* const* d_in, const int* in_sizes, int n_in,
                              void* d_out, int out_size) {
    const float* means  = (const float*)d_in[0];
    const float* cov    = (const float*)d_in[1];
    const float* color  = (const float*)d_in[2];
    const float* opac   = (const float*)d_in[3];
    const float* depths = (const float*)d_in[4];
    int N = in_sizes[4];

    k_prep<<<(N + 255) / 256, 256>>>((const float2*)means, (const float4*)cov, depths, N);
    k_scan<<<NT, 256>>>();
    k_scatter<<<(N + 255) / 256, 256>>>(depths, N);
    dim3 rg((CANDMAX + 255) / 256, NT);
    k_rankgather<<<rg, 256>>>((const float2*)means, (const float4*)cov, color, opac);
    k_composite<<<NT * BINS, 32 * NSEG>>>((float*)d_out);
}